// round 5
// baseline (speedup 1.0000x reference)
#include <cuda_runtime.h>

#define NFEAT 64

// First index i in [0, n) with idx[i] >= v (idx sorted ascending).
__device__ __forceinline__ int lower_bound_i(const int* __restrict__ idx, int n, int v) {
    int lo = 0, hi = n;
    while (lo < hi) {
        int mid = (lo + hi) >> 1;
        if (__ldg(idx + mid) < v) lo = mid + 1;
        else                      hi = mid;
    }
    return lo;
}

// out[g,f] = (sum_{i in seg g} x[i,f] * exp(x[i,f])) / (sum_{i in seg g} exp(x[i,f]))
// One block per graph. node_graph_indices is sorted, so each graph is a
// contiguous row range found by binary search. 4 warps stride rows; each lane
// owns features (2*lane, 2*lane+1) via float2 loads (one LDG.64 per warp per
// row, 256B coalesced, sequential streaming within the segment).
__global__ __launch_bounds__(128, 16) void readout_kernel(
    const float* __restrict__ feat,
    const int*   __restrict__ idx,
    float*       __restrict__ out,
    int n_atoms)
{
    const int g = blockIdx.x;

    // Redundant per-thread search: all threads converge, loads are broadcast.
    const int start = lower_bound_i(idx, n_atoms, g);
    const int end   = lower_bound_i(idx, n_atoms, g + 1);

    const int lane = threadIdx.x & 31;
    const int w    = threadIdx.x >> 5;   // warp 0..3

    float e_acc0 = 0.f, e_acc1 = 0.f;    // sum exp(x)   for features 2*lane, 2*lane+1
    float w_acc0 = 0.f, w_acc1 = 0.f;    // sum x*exp(x)

    const float2* __restrict__ f2 = reinterpret_cast<const float2*>(feat);

    #pragma unroll 4
    for (int r = start + w; r < end; r += 4) {
        float2 v = __ldg(f2 + (size_t)r * (NFEAT / 2) + lane);
        float e0 = __expf(v.x);
        float e1 = __expf(v.y);
        e_acc0 += e0;
        e_acc1 += e1;
        w_acc0 += v.x * e0;
        w_acc1 += v.y * e1;
    }

    // Cross-warp reduction through shared memory (STS.64, conflict-free).
    __shared__ float2 s_e[4][32];
    __shared__ float2 s_w[4][32];
    s_e[w][lane] = make_float2(e_acc0, e_acc1);
    s_w[w][lane] = make_float2(w_acc0, w_acc1);
    __syncthreads();

    if (threadIdx.x < NFEAT) {
        const int f = threadIdx.x;
        const float* se = reinterpret_cast<const float*>(s_e);
        const float* sw = reinterpret_cast<const float*>(s_w);
        float d = se[0 * NFEAT + f] + se[1 * NFEAT + f] + se[2 * NFEAT + f] + se[3 * NFEAT + f];
        float n = sw[0 * NFEAT + f] + sw[1 * NFEAT + f] + sw[2 * NFEAT + f] + sw[3 * NFEAT + f];
        out[(size_t)g * NFEAT + f] = (d != 0.f) ? (n / d) : 0.f;
    }
}

extern "C" void kernel_launch(void* const* d_in, const int* in_sizes, int n_in,
                              void* d_out, int out_size) {
    const float* feat = (const float*)d_in[0];   // (N_atoms, 64) float32
    const int*   idx  = (const int*)d_in[1];     // (N_atoms,)    int32, sorted
    float*       out  = (float*)d_out;           // (G, 64)       float32

    const int n_atoms    = in_sizes[1];
    const int num_graphs = out_size / NFEAT;

    readout_kernel<<<num_graphs, 128>>>(feat, idx, out, n_atoms);
}

// round 6
// speedup vs baseline: 1.3152x; 1.3152x over previous
#include <cuda_runtime.h>

#define NFEAT 64
#define MAX_GRAPHS 16384

// Segment boundaries: seg_start[g] = first row i with idx[i] >= g.
// (MAX_GRAPHS+1 entries used; __device__ global to satisfy no-alloc rules.)
__device__ int g_seg_start[MAX_GRAPHS + 1];

// idx is sorted ascending. Thread i writes seg_start[g] = i for every g in
// (idx[i-1], idx[i]]  (with idx[-1] := -1, idx[n] := num_graphs).
// Gaps between consecutive sorted values are tiny (avg segment ~122 rows),
// so the fill loop is nearly always 0 or 1 iterations.
__global__ void bounds_kernel(const int* __restrict__ idx, int n, int num_graphs) {
    int i = blockIdx.x * blockDim.x + threadIdx.x;
    if (i > n) return;
    int cur  = (i < n) ? __ldg(idx + i)     : num_graphs;
    int prev = (i > 0) ? __ldg(idx + i - 1) : -1;
    for (int g = prev + 1; g <= cur; ++g)
        g_seg_start[g] = i;
}

// out[g,f] = (sum_{i in seg g} x[i,f]*exp(x[i,f])) / (sum_{i in seg g} exp(x[i,f]))
// One block per graph; segment bounds come from the precomputed (L2-resident,
// cross-block-broadcast) g_seg_start table — no dependent-load binary search.
// 4 warps stride rows; each lane owns features (2*lane, 2*lane+1) via float2
// (one LDG.64 per warp per row = 256B coalesced sequential streaming).
__global__ __launch_bounds__(128, 16) void readout_kernel(
    const float* __restrict__ feat,
    float*       __restrict__ out)
{
    const int g = blockIdx.x;

    const int start = __ldg(&g_seg_start[g]);
    const int end   = __ldg(&g_seg_start[g + 1]);

    const int lane = threadIdx.x & 31;
    const int w    = threadIdx.x >> 5;   // warp 0..3

    float e_acc0 = 0.f, e_acc1 = 0.f;    // sum exp(x)
    float w_acc0 = 0.f, w_acc1 = 0.f;    // sum x*exp(x)

    const float2* __restrict__ f2 = reinterpret_cast<const float2*>(feat);

    #pragma unroll 4
    for (int r = start + w; r < end; r += 4) {
        float2 v = __ldg(f2 + (size_t)r * (NFEAT / 2) + lane);
        float e0 = __expf(v.x);
        float e1 = __expf(v.y);
        e_acc0 += e0;
        e_acc1 += e1;
        w_acc0 += v.x * e0;
        w_acc1 += v.y * e1;
    }

    // Cross-warp reduction through shared memory (STS.64, conflict-free).
    __shared__ float2 s_e[4][32];
    __shared__ float2 s_w[4][32];
    s_e[w][lane] = make_float2(e_acc0, e_acc1);
    s_w[w][lane] = make_float2(w_acc0, w_acc1);
    __syncthreads();

    if (threadIdx.x < NFEAT) {
        const int f = threadIdx.x;
        const float* se = reinterpret_cast<const float*>(s_e);
        const float* sw = reinterpret_cast<const float*>(s_w);
        float d = se[0 * NFEAT + f] + se[1 * NFEAT + f] + se[2 * NFEAT + f] + se[3 * NFEAT + f];
        float n = sw[0 * NFEAT + f] + sw[1 * NFEAT + f] + sw[2 * NFEAT + f] + sw[3 * NFEAT + f];
        out[(size_t)g * NFEAT + f] = (d != 0.f) ? (n / d) : 0.f;
    }
}

extern "C" void kernel_launch(void* const* d_in, const int* in_sizes, int n_in,
                              void* d_out, int out_size) {
    const float* feat = (const float*)d_in[0];   // (N_atoms, 64) float32
    const int*   idx  = (const int*)d_in[1];     // (N_atoms,)    int32, sorted
    float*       out  = (float*)d_out;           // (G, 64)       float32

    const int n_atoms    = in_sizes[1];
    const int num_graphs = out_size / NFEAT;

    bounds_kernel<<<(n_atoms + 1 + 255) / 256, 256>>>(idx, n_atoms, num_graphs);
    readout_kernel<<<num_graphs, 128>>>(feat, out);
}

// round 7
// speedup vs baseline: 1.4318x; 1.0886x over previous
#include <cuda_runtime.h>

#define NFEAT 64
#define MAX_GRAPHS 16384

// seg_start[g] = first row i with idx[i] >= g. (+1 sentinel entry)
__device__ int g_seg_start[MAX_GRAPHS + 1];

// Vectorized boundary finder: each thread owns 4 consecutive idx values
// (int4 load), writes seg_start[g]=e for every step in the sorted sequence.
__global__ void bounds_kernel(const int* __restrict__ idx, int n, int num_graphs) {
    int t = blockIdx.x * blockDim.x + threadIdx.x;
    int base = t * 4;
    if (base >= n) return;

    int prev = (base > 0) ? __ldg(idx + base - 1) : -1;

    int vals[4];
    if (base + 3 < n) {
        int4 v = __ldg(reinterpret_cast<const int4*>(idx) + t);
        vals[0] = v.x; vals[1] = v.y; vals[2] = v.z; vals[3] = v.w;
    } else {
        #pragma unroll
        for (int j = 0; j < 4; ++j)
            vals[j] = (base + j < n) ? __ldg(idx + base + j) : 0;
    }

    #pragma unroll
    for (int j = 0; j < 4; ++j) {
        int e = base + j;
        if (e >= n) break;
        int cur = vals[j];
        for (int g = prev + 1; g <= cur; ++g)
            g_seg_start[g] = e;
        if (e == n - 1)                       // trailing sentinel(s)
            for (int g = cur + 1; g <= num_graphs; ++g)
                g_seg_start[g] = n;
        prev = cur;
    }
}

// out[g,f] = (sum_seg x*exp(x)) / (sum_seg exp(x)).
// One block / graph; 4 warps; each warp streams TWO rows per iteration via
// one LDG.128 per lane (512B/warp/instr). Lane l accumulates features
// 4*(l&15)..+3 (lanes 0-15: even row of pair, 16-31: odd row). __ldcs since
// feat is single-use. Odd leftover row is folded into the final reduction.
__global__ __launch_bounds__(128, 12) void readout_kernel(
    const float* __restrict__ feat,
    float*       __restrict__ out)
{
    const int g     = blockIdx.x;
    const int start = __ldg(&g_seg_start[g]);
    const int end   = __ldg(&g_seg_start[g + 1]);

    const int lane = threadIdx.x & 31;
    const int w    = threadIdx.x >> 5;   // warp 0..3

    float4 e_acc = make_float4(0.f, 0.f, 0.f, 0.f);
    float4 w_acc = make_float4(0.f, 0.f, 0.f, 0.f);

    // Row pair (r, r+1) viewed as 512B = 32 lanes * float4.
    const float4* __restrict__ f4 = reinterpret_cast<const float4*>(feat);

    #pragma unroll 4
    for (int r = start + 2 * w; r + 1 < end; r += 8) {
        float4 v = __ldcs(f4 + (size_t)r * (NFEAT / 4) + lane);
        float e0 = __expf(v.x), e1 = __expf(v.y);
        float e2 = __expf(v.z), e3 = __expf(v.w);
        e_acc.x += e0;       e_acc.y += e1;
        e_acc.z += e2;       e_acc.w += e3;
        w_acc.x += v.x * e0; w_acc.y += v.y * e1;
        w_acc.z += v.z * e2; w_acc.w += v.w * e3;
    }

    // Fold lanes 16-31 (odd row of pair, same features) into lanes 0-15.
    const unsigned FULL = 0xffffffffu;
    e_acc.x += __shfl_down_sync(FULL, e_acc.x, 16);
    e_acc.y += __shfl_down_sync(FULL, e_acc.y, 16);
    e_acc.z += __shfl_down_sync(FULL, e_acc.z, 16);
    e_acc.w += __shfl_down_sync(FULL, e_acc.w, 16);
    w_acc.x += __shfl_down_sync(FULL, w_acc.x, 16);
    w_acc.y += __shfl_down_sync(FULL, w_acc.y, 16);
    w_acc.z += __shfl_down_sync(FULL, w_acc.z, 16);
    w_acc.w += __shfl_down_sync(FULL, w_acc.w, 16);

    __shared__ float4 s_e[4][16];
    __shared__ float4 s_w[4][16];
    if (lane < 16) {
        s_e[w][lane] = e_acc;
        s_w[w][lane] = w_acc;
    }
    __syncthreads();

    if (threadIdx.x < NFEAT) {
        const int f = threadIdx.x;
        const float* se = reinterpret_cast<const float*>(s_e);
        const float* sw = reinterpret_cast<const float*>(s_w);
        float d = se[0 * NFEAT + f] + se[1 * NFEAT + f] + se[2 * NFEAT + f] + se[3 * NFEAT + f];
        float n = sw[0 * NFEAT + f] + sw[1 * NFEAT + f] + sw[2 * NFEAT + f] + sw[3 * NFEAT + f];

        // Odd leftover row: one coalesced LDG.32 per thread.
        if ((end - start) & 1) {
            float x = __ldcs(feat + (size_t)(end - 1) * NFEAT + f);
            float e = __expf(x);
            d += e;
            n += x * e;
        }
        out[(size_t)g * NFEAT + f] = (d != 0.f) ? (n / d) : 0.f;
    }
}

extern "C" void kernel_launch(void* const* d_in, const int* in_sizes, int n_in,
                              void* d_out, int out_size) {
    const float* feat = (const float*)d_in[0];   // (N_atoms, 64) float32
    const int*   idx  = (const int*)d_in[1];     // (N_atoms,)    int32, sorted
    float*       out  = (float*)d_out;           // (G, 64)       float32

    const int n_atoms    = in_sizes[1];
    const int num_graphs = out_size / NFEAT;

    int bthreads = (n_atoms + 3) / 4;
    bounds_kernel<<<(bthreads + 255) / 256, 256>>>(idx, n_atoms, num_graphs);
    readout_kernel<<<num_graphs, 128>>>(feat, out);
}